// round 14
// baseline (speedup 1.0000x reference)
#include <cuda_runtime.h>
#include <cstdint>

// Conv2d VALID: x[32,64,112,112] f32, w[128,64,3,3] f32 -> out[32,128,110,110] f32
// Implicit GEMM via mma.sync.m16n8k8 tf32.
// Round 14: R13 pipeline + s-invariant B windows.
//   Loop order (ci-half, r, s). Bs holds the RAW input window [k][osub][col 0..67]
//   (s applied at fragment-LDS time, affine) -> B gathered 6x per CTA, not 18x.
//   Window gather spread across the 3 taps of the prior stage (LDG pre-compute,
//   STS post-compute, double-buffered windows). A per-tap cp.async double buffer.

namespace {

constexpr int CIN = 64, COUT = 128, H = 112, W = 112, OH = 110, OW = 110;
constexpr int HW = H * W;
constexpr int A_STRIDE = 40;                 // pair-bank (4lr+lq) bijective
constexpr int A_BYTES = 128 * A_STRIDE * 4;  // 20480
constexpr int B_RS = 68;                     // floats per (k,osub) row; 136 % 32 == 8
constexpr int B_BYTES = 64 * B_RS * 4;       // 17408
constexpr int B_ELEMS = 32 * 2 * B_RS;       // 4352 floats per window
constexpr int SM_TOTAL = 2 * A_BYTES + 2 * B_BYTES;  // 75776

__device__ float g_A_pre[18 * 4096];  // [kc = half*9 + r*3 + s][co 128][perm-col 32]

__device__ __forceinline__ float to_tf32(float v) {
    float o;
    asm("cvt.rna.tf32.f32 %0, %1;" : "=f"(o) : "f"(v));
    return o;
}
__device__ __forceinline__ uint32_t smem_u32(const void* p) {
    uint32_t a;
    asm("{ .reg .u64 t; cvta.to.shared.u64 t, %1; cvt.u32.u64 %0, t; }" : "=r"(a) : "l"(p));
    return a;
}
__device__ __forceinline__ void cp_async16(uint32_t dst, const void* src) {
    asm volatile("cp.async.ca.shared.global [%0], [%1], 16;" :: "r"(dst), "l"(src));
}
__device__ __forceinline__ void cp_commit() {
    asm volatile("cp.async.commit_group;" ::: "memory");
}
__device__ __forceinline__ void cp_wait0() {
    asm volatile("cp.async.wait_group 0;" ::: "memory");
}

// perm-col = g*8 + q*2 + e  <->  k = g*8 + q + 4*e ;  kc = half*9 + r*3 + s
__global__ void prep_weights(const float* __restrict__ w) {
    int idx = blockIdx.x * 256 + threadIdx.x;   // 0 .. 73727
    int kc  = idx >> 12;
    int rem = idx & 4095;
    int co  = rem >> 5;
    int col = rem & 31;
    int g = col >> 3, tt = col & 7, q = tt >> 1, e = tt & 1;
    int k    = g * 8 + q + 4 * e;
    int half = kc / 9;
    int rs   = kc - half * 9;
    int ci   = half * 32 + k;
    g_A_pre[idx] = to_tf32(w[((size_t)co * CIN + ci) * 9 + rs]);
}

__global__ __launch_bounds__(256, 2)
void conv_mma(const float* __restrict__ x, float* __restrict__ out)
{
    extern __shared__ char sm[];   // A0 | A1 | B0 | B1

    const int tid  = threadIdx.x;
    const int lane = tid & 31;
    const int wid  = tid >> 5;
    const int wm   = wid >> 2;
    const int wn   = wid & 3;
    const int lr   = lane >> 2;
    const int lq   = lane & 3;

    const int ow0 = blockIdx.x * 64;
    const int oh0 = blockIdx.y * 2;
    const int bb  = blockIdx.z;

    const float* xb = x + (size_t)bb * CIN * HW;
    const uint32_t smbase = smem_u32(sm);

    uint32_t a_dst[4];
#pragma unroll
    for (int i = 0; i < 4; ++i) {
        int idx = tid + 256 * i;
        a_dst[i] = smbase + (uint32_t)((idx >> 3) * A_STRIDE + (idx & 7) * 4) * 4;
    }

    float acc[4][4][4];
#pragma unroll
    for (int i = 0; i < 4; i++)
#pragma unroll
        for (int j = 0; j < 4; j++)
#pragma unroll
            for (int k = 0; k < 4; k++) acc[i][j][k] = 0.0f;

    // ---- prologue: full B window for stage 0 (half=0, r=0), A chunk 0 ----
#pragma unroll
    for (int i = 0; i < 17; ++i) {
        int flat = tid + 256 * i;
        if (flat < B_ELEMS) {
            int k    = flat / (2 * B_RS);
            int rem2 = flat - k * (2 * B_RS);
            int osub = rem2 / B_RS;
            int col  = rem2 - osub * B_RS;
            float v = to_tf32(xb[(size_t)k * HW + (oh0 + osub) * W + min(ow0 + col, W - 1)]);
            *(float*)(sm + 2 * A_BYTES + (size_t)flat * 4) = v;
        }
    }
    {
        const float4* src = (const float4*)g_A_pre;
#pragma unroll
        for (int i = 0; i < 4; ++i) cp_async16(a_dst[i], src + tid + 256 * i);
        cp_commit();
    }

    for (int j = 0; j < 6; ++j) {               // stage = (half, r)
        const int jn    = j + 1;
        const int halfn = jn / 3;               // next stage decode (jn<6)
        const int rn    = jn - halfn * 3;

        for (int s = 0; s < 3; ++s) {
            const int kc = j * 3 + s;

            cp_wait0();
            __syncthreads();   // A[kc] ready; all warps done with prior tap

            // ---- A prefetch chunk kc+1 ----
            if (kc < 17) {
                const float4* src = (const float4*)(g_A_pre + (kc + 1) * 4096);
                const uint32_t ab = ((kc + 1) & 1) ? (uint32_t)A_BYTES : 0u;
#pragma unroll
                for (int i = 0; i < 4; ++i) cp_async16(a_dst[i] + ab, src + tid + 256 * i);
                cp_commit();
            }

            // ---- B slice gather for stage j+1 (slots s*6 .. ) ----
            float pv[6];
            const int ns = (s == 2) ? 5 : 6;
            if (j < 5) {
                const float* srcb = xb + (size_t)halfn * 32 * HW + (oh0 + rn) * W;
#pragma unroll
                for (int u = 0; u < 6; ++u) {
                    pv[u] = 0.0f;
                    if (u < ns) {
                        int flat = tid + 256 * (s * 6 + u);
                        if (flat < B_ELEMS) {
                            int k    = flat / (2 * B_RS);
                            int rem2 = flat - k * (2 * B_RS);
                            int osub = rem2 / B_RS;
                            int col  = rem2 - osub * B_RS;
                            pv[u] = srcb[(size_t)k * HW + osub * W + min(ow0 + col, W - 1)];
                        }
                    }
                }
            }

            // ---- compute tap ----
            const float* As = (const float*)(sm + (kc & 1) * A_BYTES);
            const float* Bw = (const float*)(sm + 2 * A_BYTES + (j & 1) * B_BYTES)
                              + (wn >> 1) * B_RS + (wn & 1) * 32 + s + lr;

#pragma unroll
            for (int g = 0; g < 4; ++g) {
                uint32_t a[4][4];
#pragma unroll
                for (int mf = 0; mf < 4; ++mf) {
                    int row = wm * 64 + mf * 16 + lr;
                    float2 v02 = *(const float2*)(As + row * A_STRIDE + g * 8 + lq * 2);
                    float2 v13 = *(const float2*)(As + (row + 8) * A_STRIDE + g * 8 + lq * 2);
                    a[mf][0] = __float_as_uint(v02.x);
                    a[mf][1] = __float_as_uint(v13.x);
                    a[mf][2] = __float_as_uint(v02.y);
                    a[mf][3] = __float_as_uint(v13.y);
                }
                uint32_t b[4][2];
#pragma unroll
                for (int nf = 0; nf < 4; ++nf) {
                    // k row = g*8+lq (and +4); bank = 8lq + lr + const -> conflict-free
                    b[nf][0] = __float_as_uint(Bw[(g * 8 + lq) * 2 * B_RS + nf * 8]);
                    b[nf][1] = __float_as_uint(Bw[(g * 8 + lq + 4) * 2 * B_RS + nf * 8]);
                }
#pragma unroll
                for (int mf = 0; mf < 4; ++mf)
#pragma unroll
                    for (int nf = 0; nf < 4; ++nf) {
                        asm volatile(
                            "mma.sync.aligned.m16n8k8.row.col.f32.tf32.tf32.f32 "
                            "{%0,%1,%2,%3}, {%4,%5,%6,%7}, {%8,%9}, {%0,%1,%2,%3};"
                            : "+f"(acc[mf][nf][0]), "+f"(acc[mf][nf][1]),
                              "+f"(acc[mf][nf][2]), "+f"(acc[mf][nf][3])
                            : "r"(a[mf][0]), "r"(a[mf][1]), "r"(a[mf][2]), "r"(a[mf][3]),
                              "r"(b[nf][0]), "r"(b[nf][1]));
                    }
            }

            // ---- STS gathered slice into next window buffer ----
            if (j < 5) {
                char* bd = sm + 2 * A_BYTES + ((j + 1) & 1) * B_BYTES;
#pragma unroll
                for (int u = 0; u < 6; ++u) {
                    if (u < ns) {
                        int flat = tid + 256 * (s * 6 + u);
                        if (flat < B_ELEMS)
                            *(float*)(bd + (size_t)flat * 4) = to_tf32(pv[u]);
                    }
                }
            }
        }
    }

    // ---- epilogue: direct STG.64 (even ow, pairs in-bounds) ----
#pragma unroll
    for (int mf = 0; mf < 4; ++mf) {
#pragma unroll
        for (int nf = 0; nf < 4; ++nf) {
            int nglob = wn * 32 + nf * 8 + lq * 2;    // even
            int osub  = nglob >> 6;
            int ow    = ow0 + (nglob & 63);
            int oh    = oh0 + osub;
            if (ow < OW) {
                int co0 = wm * 64 + mf * 16 + lr;
                float* p0 = out + (((size_t)bb * COUT + co0) * OH + oh) * OW + ow;
                *(float2*)p0 = make_float2(acc[mf][nf][0], acc[mf][nf][1]);
                float* p1 = p0 + (size_t)8 * OH * OW;
                *(float2*)p1 = make_float2(acc[mf][nf][2], acc[mf][nf][3]);
            }
        }
    }
}

} // namespace

extern "C" void kernel_launch(void* const* d_in, const int* in_sizes, int n_in,
                              void* d_out, int out_size)
{
    const float* x = (const float*)d_in[0];
    const float* w = (const float*)d_in[1];
    float* out = (float*)d_out;

    cudaFuncSetAttribute(conv_mma, cudaFuncAttributeMaxDynamicSharedMemorySize, SM_TOTAL);

    prep_weights<<<18 * 4096 / 256, 256>>>(w);

    dim3 grid(2, 55, 32);   // ow tiles (2x64), oh pairs, batch
    conv_mma<<<grid, 256, SM_TOTAL>>>(x, out);
}

// round 15
// speedup vs baseline: 1.0556x; 1.0556x over previous
#include <cuda_runtime.h>
#include <cstdint>

// Conv2d VALID: x[32,64,112,112] f32, w[128,64,3,3] f32 -> out[32,128,110,110] f32
// Implicit GEMM via mma.sync.m16n8k8 tf32.
// Round 15: R14 (s-invariant B windows, gathered 6x per CTA) with the gather
// addressing fully hoisted: per-thread global offsets goff[17] computed once
// (B_ELEMS = 17*256 exactly -> every slot valid), s-loop unrolled so slot
// indices are compile-time, STS addresses affine. A per-tap cp.async buffer.

namespace {

constexpr int CIN = 64, COUT = 128, H = 112, W = 112, OH = 110, OW = 110;
constexpr int HW = H * W;
constexpr int A_STRIDE = 40;                 // pair-bank (4lr+lq) bijective
constexpr int A_BYTES = 128 * A_STRIDE * 4;  // 20480
constexpr int B_RS = 68;                     // floats per (k,osub) row; 136 % 32 == 8
constexpr int B_BYTES = 64 * B_RS * 4;       // 17408
constexpr int B_ELEMS = 32 * 2 * B_RS;       // 4352 = 17 * 256
constexpr int SM_TOTAL = 2 * A_BYTES + 2 * B_BYTES;  // 75776

__device__ float g_A_pre[18 * 4096];  // [kc = half*9 + r*3 + s][co 128][perm-col 32]

__device__ __forceinline__ float to_tf32(float v) {
    float o;
    asm("cvt.rna.tf32.f32 %0, %1;" : "=f"(o) : "f"(v));
    return o;
}
__device__ __forceinline__ uint32_t smem_u32(const void* p) {
    uint32_t a;
    asm("{ .reg .u64 t; cvta.to.shared.u64 t, %1; cvt.u32.u64 %0, t; }" : "=r"(a) : "l"(p));
    return a;
}
__device__ __forceinline__ void cp_async16(uint32_t dst, const void* src) {
    asm volatile("cp.async.ca.shared.global [%0], [%1], 16;" :: "r"(dst), "l"(src));
}
__device__ __forceinline__ void cp_commit() {
    asm volatile("cp.async.commit_group;" ::: "memory");
}
__device__ __forceinline__ void cp_wait0() {
    asm volatile("cp.async.wait_group 0;" ::: "memory");
}
__device__ __forceinline__ void sts_f32(uint32_t addr, float v) {
    asm volatile("st.shared.f32 [%0], %1;" :: "r"(addr), "f"(v) : "memory");
}

// perm-col = g*8 + q*2 + e  <->  k = g*8 + q + 4*e ;  kc = half*9 + r*3 + s
__global__ void prep_weights(const float* __restrict__ w) {
    int idx = blockIdx.x * 256 + threadIdx.x;   // 0 .. 73727
    int kc  = idx >> 12;
    int rem = idx & 4095;
    int co  = rem >> 5;
    int col = rem & 31;
    int g = col >> 3, tt = col & 7, q = tt >> 1, e = tt & 1;
    int k    = g * 8 + q + 4 * e;
    int half = kc / 9;
    int rs   = kc - half * 9;
    int ci   = half * 32 + k;
    g_A_pre[idx] = to_tf32(w[((size_t)co * CIN + ci) * 9 + rs]);
}

__global__ __launch_bounds__(256, 2)
void conv_mma(const float* __restrict__ x, float* __restrict__ out)
{
    extern __shared__ char sm[];   // A0 | A1 | B0 | B1

    const int tid  = threadIdx.x;
    const int lane = tid & 31;
    const int wid  = tid >> 5;
    const int wm   = wid >> 2;
    const int wn   = wid & 3;
    const int lr   = lane >> 2;
    const int lq   = lane & 3;

    const int ow0 = blockIdx.x * 64;
    const int oh0 = blockIdx.y * 2;
    const int bb  = blockIdx.z;

    const float* xb = x + (size_t)bb * CIN * HW;
    const uint32_t smbase = smem_u32(sm);

    // ---- hoisted per-thread gather offsets (chunk-invariant) ----
    uint32_t goff[17];
#pragma unroll
    for (int i = 0; i < 17; ++i) {
        int flat = tid + 256 * i;            // < 4352 always
        int k    = flat / 136;               // 2*B_RS
        int rem2 = flat - k * 136;
        int osub = rem2 / 68;
        int col  = rem2 - osub * 68;
        goff[i]  = (uint32_t)(k * HW + osub * W + min(ow0 + col, W - 1));
    }
    // STS base: byte addr of slot 0 = B-window base + tid*4; slot i adds 1024*i
    const uint32_t bsts0 = smbase + (uint32_t)(2 * A_BYTES) + (uint32_t)tid * 4u;

    uint32_t a_dst[4];
#pragma unroll
    for (int i = 0; i < 4; ++i) {
        int idx = tid + 256 * i;
        a_dst[i] = smbase + (uint32_t)((idx >> 3) * A_STRIDE + (idx & 7) * 4) * 4;
    }

    float acc[4][4][4];
#pragma unroll
    for (int i = 0; i < 4; i++)
#pragma unroll
        for (int j = 0; j < 4; j++)
#pragma unroll
            for (int k = 0; k < 4; k++) acc[i][j][k] = 0.0f;

    // ---- prologue: full B window for stage 0 (half=0, r=0), A chunk 0 ----
    {
        const float* srcb0 = xb + oh0 * W;
#pragma unroll
        for (int i = 0; i < 17; ++i)
            sts_f32(bsts0 + 1024u * i, to_tf32(srcb0[goff[i]]));

        const float4* src = (const float4*)g_A_pre;
#pragma unroll
        for (int i = 0; i < 4; ++i) cp_async16(a_dst[i], src + tid + 256 * i);
        cp_commit();
    }

    for (int j = 0; j < 6; ++j) {               // stage = (half, r)
        const int jn    = j + 1;
        const int halfn = jn / 3;
        const int rn    = jn - halfn * 3;
        const float* srcb = xb + (size_t)halfn * 32 * HW + (oh0 + rn) * W;

#pragma unroll
        for (int s = 0; s < 3; ++s) {
            const int kc = j * 3 + s;
            const int ns = (s == 2) ? 5 : 6;    // 6+6+5 = 17 slots

            cp_wait0();
            __syncthreads();   // A[kc] ready; all warps done with prior tap

            // ---- A prefetch chunk kc+1 ----
            if (kc < 17) {
                const float4* src = (const float4*)(g_A_pre + (kc + 1) * 4096);
                const uint32_t ab = ((kc + 1) & 1) ? (uint32_t)A_BYTES : 0u;
#pragma unroll
                for (int i = 0; i < 4; ++i) cp_async16(a_dst[i] + ab, src + tid + 256 * i);
                cp_commit();
            }

            // ---- B slice gather for stage j+1 (slots s*6 ..) ----
            float pv[6];
            if (j < 5) {
#pragma unroll
                for (int u = 0; u < 6; ++u)
                    pv[u] = (u < ns) ? srcb[goff[s * 6 + u]] : 0.0f;
            }

            // ---- compute tap ----
            const float* As = (const float*)(sm + (kc & 1) * A_BYTES);
            const float* Bw = (const float*)(sm + 2 * A_BYTES + (j & 1) * B_BYTES)
                              + (wn >> 1) * B_RS + (wn & 1) * 32 + s + lr;

#pragma unroll
            for (int g = 0; g < 4; ++g) {
                uint32_t a[4][4];
#pragma unroll
                for (int mf = 0; mf < 4; ++mf) {
                    int row = wm * 64 + mf * 16 + lr;
                    float2 v02 = *(const float2*)(As + row * A_STRIDE + g * 8 + lq * 2);
                    float2 v13 = *(const float2*)(As + (row + 8) * A_STRIDE + g * 8 + lq * 2);
                    a[mf][0] = __float_as_uint(v02.x);
                    a[mf][1] = __float_as_uint(v13.x);
                    a[mf][2] = __float_as_uint(v02.y);
                    a[mf][3] = __float_as_uint(v13.y);
                }
                uint32_t b[4][2];
#pragma unroll
                for (int nf = 0; nf < 4; ++nf) {
                    b[nf][0] = __float_as_uint(Bw[(g * 8 + lq) * 2 * B_RS + nf * 8]);
                    b[nf][1] = __float_as_uint(Bw[(g * 8 + lq + 4) * 2 * B_RS + nf * 8]);
                }
#pragma unroll
                for (int mf = 0; mf < 4; ++mf)
#pragma unroll
                    for (int nf = 0; nf < 4; ++nf) {
                        asm volatile(
                            "mma.sync.aligned.m16n8k8.row.col.f32.tf32.tf32.f32 "
                            "{%0,%1,%2,%3}, {%4,%5,%6,%7}, {%8,%9}, {%0,%1,%2,%3};"
                            : "+f"(acc[mf][nf][0]), "+f"(acc[mf][nf][1]),
                              "+f"(acc[mf][nf][2]), "+f"(acc[mf][nf][3])
                            : "r"(a[mf][0]), "r"(a[mf][1]), "r"(a[mf][2]), "r"(a[mf][3]),
                              "r"(b[nf][0]), "r"(b[nf][1]));
                    }
            }

            // ---- STS gathered slice into next window buffer (affine addrs) ----
            if (j < 5) {
                const uint32_t bd = bsts0 + (((j + 1) & 1) ? (uint32_t)B_BYTES : 0u);
#pragma unroll
                for (int u = 0; u < 6; ++u)
                    if (u < ns)
                        sts_f32(bd + 1024u * (s * 6 + u), to_tf32(pv[u]));
            }
        }
    }

    // ---- epilogue: direct STG.64 (even ow, pairs in-bounds) ----
#pragma unroll
    for (int mf = 0; mf < 4; ++mf) {
#pragma unroll
        for (int nf = 0; nf < 4; ++nf) {
            int nglob = wn * 32 + nf * 8 + lq * 2;    // even
            int osub  = nglob >> 6;
            int ow    = ow0 + (nglob & 63);
            int oh    = oh0 + osub;
            if (ow < OW) {
                int co0 = wm * 64 + mf * 16 + lr;
                float* p0 = out + (((size_t)bb * COUT + co0) * OH + oh) * OW + ow;
                *(float2*)p0 = make_float2(acc[mf][nf][0], acc[mf][nf][1]);
                float* p1 = p0 + (size_t)8 * OH * OW;
                *(float2*)p1 = make_float2(acc[mf][nf][2], acc[mf][nf][3]);
            }
        }
    }
}

} // namespace

extern "C" void kernel_launch(void* const* d_in, const int* in_sizes, int n_in,
                              void* d_out, int out_size)
{
    const float* x = (const float*)d_in[0];
    const float* w = (const float*)d_in[1];
    float* out = (float*)d_out;

    cudaFuncSetAttribute(conv_mma, cudaFuncAttributeMaxDynamicSharedMemorySize, SM_TOTAL);

    prep_weights<<<18 * 4096 / 256, 256>>>(w);

    dim3 grid(2, 55, 32);   // ow tiles (2x64), oh pairs, batch
    conv_mma<<<grid, 256, SM_TOTAL>>>(x, out);
}